// round 15
// baseline (speedup 1.0000x reference)
#include <cuda_runtime.h>
#include <cuda_bf16.h>
#include <cuda_fp16.h>
#include <cuda_fp8.h>
#include <cstdint>
#include <math.h>

#define BATCH 4
#define CH    512
#define HW    4096
#define NGRP  32
#define CPG   16

static const size_t CHW = (size_t)CH * HW;
#define CC (CH * CH)

// ---------------- scratch ----------------
__device__ __nv_bfloat16 g_xnT [BATCH * CH * HW];   // [hw, c] bf16
__device__ uint8_t       g_q   [BATCH * CH * HW];   // [hw, c] fp8
__device__ uint8_t       g_k   [BATCH * CH * HW];   // [hw, c] fp8
__device__ uint8_t       g_v   [BATCH * CH * HW];   // [c, hw] fp8
__device__ uint8_t       g_o28 [BATCH * CH * HW];   // [hw, c] fp8, x256
__device__ __nv_bfloat16 g_w   [4 * CH * CH];       // wq, wk, wv, wp bf16
__device__ uint8_t       g_w8  [CH * CH];           // wp fp8, x64
__device__ float         g_bqk [1024];              // concat(bq, bk)

// ---------------- PTX helpers (family-portable) ----------------
__device__ __forceinline__ uint32_t smem_u32(const void* p) {
    uint32_t a;
    asm("{ .reg .u64 t; cvta.to.shared.u64 t, %1; cvt.u32.u64 %0, t; }"
        : "=r"(a) : "l"(p));
    return a;
}
__device__ __forceinline__ void cp16(uint32_t s, const void* g) {
    asm volatile("cp.async.cg.shared.global [%0], [%1], 16;"
                 :: "r"(s), "l"(__cvta_generic_to_global(g)) : "memory");
}
#define CP_COMMIT() asm volatile("cp.async.commit_group;" ::: "memory")
#define CP_WAIT1()  asm volatile("cp.async.wait_group 1;"  ::: "memory")
#define CP_WAIT0()  asm volatile("cp.async.wait_group 0;"  ::: "memory")

__device__ __forceinline__ void ldsm_x4(uint32_t* r, uint32_t addr) {
    asm volatile("ldmatrix.sync.aligned.m8n8.x4.shared.b16 {%0,%1,%2,%3}, [%4];"
        : "=r"(r[0]), "=r"(r[1]), "=r"(r[2]), "=r"(r[3]) : "r"(addr));
}
__device__ __forceinline__ void mma16816(float* c, const uint32_t* a,
                                         uint32_t b0, uint32_t b1) {
    asm volatile(
        "mma.sync.aligned.m16n8k16.row.col.f32.bf16.bf16.f32 "
        "{%0,%1,%2,%3}, {%4,%5,%6,%7}, {%8,%9}, {%0,%1,%2,%3};"
        : "+f"(c[0]), "+f"(c[1]), "+f"(c[2]), "+f"(c[3])
        : "r"(a[0]), "r"(a[1]), "r"(a[2]), "r"(a[3]), "r"(b0), "r"(b1));
}
__device__ __forceinline__ void mma_f8h(uint32_t* c, const uint32_t* a,
                                        uint32_t b0, uint32_t b1) {
    asm volatile(
        "mma.sync.aligned.m16n8k32.row.col.f16.e4m3.e4m3.f16 "
        "{%0,%1}, {%2,%3,%4,%5}, {%6,%7}, {%0,%1};"
        : "+r"(c[0]), "+r"(c[1])
        : "r"(a[0]), "r"(a[1]), "r"(a[2]), "r"(a[3]), "r"(b0), "r"(b1));
}
__device__ __forceinline__ uint16_t f2_to_e4m3x2(float x0, float x1) {
    return (uint16_t)__nv_cvt_float2_to_fp8x2(make_float2(x0, x1),
                                              __NV_SATFINITE, __NV_E4M3);
}
__device__ __forceinline__ void sts16(uint32_t addr, uint16_t v) {
    asm volatile("st.shared.u16 [%0], %1;" :: "r"(addr), "h"(v) : "memory");
}
__device__ __forceinline__ void stsf(uint32_t addr, float v) {
    asm volatile("st.shared.f32 [%0], %1;" :: "r"(addr), "f"(v) : "memory");
}
__device__ __forceinline__ float ldsf(uint32_t addr) {
    float v;
    asm volatile("ld.shared.f32 %0, [%1];" : "=f"(v) : "r"(addr));
    return v;
}

// ---------------------------------------------------------------------------
// GroupNorm fused with transpose: x [c, hw] fp32 -> xnT [hw, c] bf16
// ---------------------------------------------------------------------------
__global__ __launch_bounds__(256) void groupnorm_t_kernel(
    const float* __restrict__ x, const float* __restrict__ scale,
    const float* __restrict__ bias, __nv_bfloat16* __restrict__ xnT)
{
    const int b = blockIdx.x / NGRP, g = blockIdx.x % NGRP;
    const size_t base = ((size_t)b * CH + (size_t)g * CPG) * HW;
    const int n4 = CPG * HW / 4;

    const float4* xin = reinterpret_cast<const float4*>(x + base);
    float s = 0.f, ss = 0.f;
    for (int i = threadIdx.x; i < n4; i += 256) {
        float4 t = xin[i];
        s  += t.x + t.y + t.z + t.w;
        ss += t.x * t.x + t.y * t.y + t.z * t.z + t.w * t.w;
    }
    __shared__ float r1[256], r2[256];
    r1[threadIdx.x] = s; r2[threadIdx.x] = ss;
    __syncthreads();
    for (int off = 128; off > 0; off >>= 1) {
        if (threadIdx.x < off) {
            r1[threadIdx.x] += r1[threadIdx.x + off];
            r2[threadIdx.x] += r2[threadIdx.x + off];
        }
        __syncthreads();
    }
    const float inv_n = 1.f / (float)(CPG * HW);
    const float mean = r1[0] * inv_n;
    const float var  = fmaxf(r2[0] * inv_n - mean * mean, 0.f);
    const float rstd = rsqrtf(var + 1e-6f);

    const int cl  = threadIdx.x >> 4;
    const int seg = threadIdx.x & 15;
    const float a = scale[g * CPG + cl] * rstd;
    const float d = bias[g * CPG + cl] - mean * a;

    __shared__ uint16_t tile[16][272];
    const float* xrow = x + base + (size_t)cl * HW;
    __nv_bfloat16* outb = xnT + ((size_t)b * HW) * CH + g * CPG;

    for (int hw0 = 0; hw0 < HW; hw0 += 256) {
        const float4* src = reinterpret_cast<const float4*>(xrow + hw0 + seg * 16);
        #pragma unroll
        for (int j = 0; j < 4; j++) {
            float4 t = src[j];
            __nv_bfloat162 h0 = __floats2bfloat162_rn(t.x * a + d, t.y * a + d);
            __nv_bfloat162 h1 = __floats2bfloat162_rn(t.z * a + d, t.w * a + d);
            *reinterpret_cast<uint32_t*>(&tile[cl][seg * 16 + j * 4])
                = *reinterpret_cast<uint32_t*>(&h0);
            *reinterpret_cast<uint32_t*>(&tile[cl][seg * 16 + j * 4 + 2])
                = *reinterpret_cast<uint32_t*>(&h1);
        }
        __syncthreads();
        uint16_t rowv[16];
        #pragma unroll
        for (int i = 0; i < 16; i++) rowv[i] = tile[i][threadIdx.x];
        uint4* dst = reinterpret_cast<uint4*>(outb + (size_t)(hw0 + threadIdx.x) * CH);
        dst[0] = *reinterpret_cast<uint4*>(&rowv[0]);
        dst[1] = *reinterpret_cast<uint4*>(&rowv[8]);
        __syncthreads();
    }
}

// ---------------------------------------------------------------------------
// weights: fp32 -> bf16; wp also -> fp8 x64; concat(bq,bk)
// ---------------------------------------------------------------------------
__global__ __launch_bounds__(256) void cvt_w_kernel(
    const float* __restrict__ a, const float* __restrict__ b,
    const float* __restrict__ c, const float* __restrict__ d,
    const float* __restrict__ bq, const float* __restrict__ bk,
    __nv_bfloat16* __restrict__ w, uint8_t* __restrict__ w8,
    float* __restrict__ bqk)
{
    const int i = blockIdx.x * 256 + threadIdx.x;
    const float* s = (blockIdx.y == 0) ? a : (blockIdx.y == 1) ? b : (blockIdx.y == 2) ? c : d;
    const float val = s[i];
    w[(size_t)blockIdx.y * CC + i] = __float2bfloat16(val);
    if (blockIdx.y == 3)
        w8[i] = (uint8_t)__nv_cvt_float_to_fp8(val * 64.f, __NV_SATFINITE, __NV_E4M3);
    if (blockIdx.y == 0 && i < 1024)
        bqk[i] = (i < 512) ? bq[i] : bk[i - 512];
}

// ---------------------------------------------------------------------------
// bf16 GEMM: D = A@B^T + bias_n. OT 2 = fp8 out; OT 3 = dual fp8 out.
// 128x128 tile, 8 warps 4Mx2N, 3 stages.
// ---------------------------------------------------------------------------
#define PITCH  144
#define OPSZ   18432
#define STG_SZ 36864
#define SMEM_TC 110592

template<int OT>
__global__ void __launch_bounds__(256, 2) gemm_tc(
    const void* __restrict__ Ag, const void* __restrict__ Bg,
    void* __restrict__ Cout, void* __restrict__ Cout2,
    const float* __restrict__ bias_m, const float* __restrict__ bias_n,
    int M, int N, int K, float alpha,
    size_t sA, size_t sB, size_t sC)
{
    extern __shared__ __align__(16) char smem[];
    const uint32_t sb = smem_u32(smem);

    const int tid  = threadIdx.x;
    const int lane = tid & 31;
    const int wid  = tid >> 5;
    const int wm   = wid >> 1;
    const int wn   = wid & 1;
    const int bm = blockIdx.y * 128;
    const int bn = blockIdx.x * 128;

    const uint8_t* Ab = (const uint8_t*)Ag + ((size_t)blockIdx.z * sA + (size_t)bm * K) * 2;
    const uint8_t* Bb = (const uint8_t*)Bg + ((size_t)blockIdx.z * sB + (size_t)bn * K) * 2;

    int rr[4];
    uint32_t so[4], go[4];
    #pragma unroll
    for (int j = 0; j < 4; j++) {
        const int idx = tid + j * 256;
        rr[j] = idx >> 3;
        const int cc = idx & 7;
        so[j] = (uint32_t)rr[j] * PITCH + cc * 16;
        go[j] = cc * 16;
    }

    const int nk = K >> 6;

    #pragma unroll
    for (int s = 0; s < 2; s++) {
        const uint32_t kb = (uint32_t)s * 128;
        const uint32_t st = sb + s * STG_SZ;
        #pragma unroll
        for (int j = 0; j < 4; j++) {
            cp16(st + so[j],        Ab + (size_t)rr[j] * K * 2 + kb + go[j]);
            cp16(st + OPSZ + so[j], Bb + (size_t)rr[j] * K * 2 + kb + go[j]);
        }
        CP_COMMIT();
    }

    float acc[2][8][4];
    #pragma unroll
    for (int i = 0; i < 2; i++)
        #pragma unroll
        for (int j = 0; j < 8; j++)
            #pragma unroll
            for (int t = 0; t < 4; t++) acc[i][j][t] = 0.f;

    const uint32_t lrow = lane & 15;
    const uint32_t lsel = (lane >> 4) * 16;

    int buf = 0;
    for (int ck = 0; ck < nk; ck++) {
        CP_WAIT1();
        __syncthreads();

        if (ck + 2 < nk) {
            const uint32_t kb = (uint32_t)(ck + 2) * 128;
            const uint32_t st = sb + ((buf + 2) % 3) * STG_SZ;
            #pragma unroll
            for (int j = 0; j < 4; j++) {
                cp16(st + so[j],        Ab + (size_t)rr[j] * K * 2 + kb + go[j]);
                cp16(st + OPSZ + so[j], Bb + (size_t)rr[j] * K * 2 + kb + go[j]);
            }
        }
        CP_COMMIT();

        const uint32_t sa  = sb + buf * STG_SZ;
        const uint32_t sbm = sa + OPSZ;
        #pragma unroll
        for (int kf = 0; kf < 4; kf++) {
            const uint32_t kofs = kf * 32 + lsel;
            uint32_t ar[2][4];
            #pragma unroll
            for (int mi = 0; mi < 2; mi++)
                ldsm_x4(ar[mi], sa + (wm * 32 + mi * 16 + lrow) * PITCH + kofs);
            uint32_t br[4][4];
            #pragma unroll
            for (int nb = 0; nb < 4; nb++)
                ldsm_x4(br[nb], sbm + (wn * 64 + nb * 16 + lrow) * PITCH + kofs);
            #pragma unroll
            for (int mi = 0; mi < 2; mi++)
                #pragma unroll
                for (int nj = 0; nj < 8; nj++) {
                    const int nb = nj >> 1, od = nj & 1;
                    mma16816(acc[mi][nj], ar[mi], br[nb][od], br[nb][od + 2]);
                }
        }
        buf = (buf + 1) % 3;
    }

    const int gid = lane >> 2, tig = lane & 3;
    #pragma unroll
    for (int mi = 0; mi < 2; mi++) {
        #pragma unroll
        for (int r2 = 0; r2 < 2; r2++) {
            const int m = bm + wm * 32 + mi * 16 + gid + r2 * 8;
            const float bmv = bias_m ? bias_m[m] : 0.f;
            #pragma unroll
            for (int nj = 0; nj < 8; nj++) {
                const int n = bn + wn * 64 + nj * 8 + tig * 2;
                float x0 = acc[mi][nj][r2 * 2]     * alpha + bmv;
                float x1 = acc[mi][nj][r2 * 2 + 1] * alpha + bmv;
                if (bias_n) { x0 += bias_n[n]; x1 += bias_n[n + 1]; }
                if (OT == 2) {
                    *reinterpret_cast<uint16_t*>(
                        (uint8_t*)Cout + (size_t)blockIdx.z * sC + (size_t)m * N + n)
                        = f2_to_e4m3x2(x0, x1);
                } else {
                    uint8_t* dst = (n < 512) ? (uint8_t*)Cout : (uint8_t*)Cout2;
                    *reinterpret_cast<uint16_t*>(
                        dst + (size_t)blockIdx.z * sC + (size_t)m * 512 + (n & 511))
                        = f2_to_e4m3x2(x0, x1);
                }
            }
        }
    }
}

// ---------------------------------------------------------------------------
// Fused single-pass attention: per CTA = (i-tile of 128 q rows, batch).
// q_i resident in smem; stream k_j, v_j; o accumulated in f16 regs; row sums
// in regs; normalize in epilogue. No max-subtraction (scores bounded ~1.5).
// 256 threads, 8 warps (4M x 2N of 32x64). XOR-swizzled smem, no padding.
//   Q: 128 x 512 B (65536)   K: 128 x 512 B (65536)
//   V: 512 x 128 B (65536)   P: 128 x 128 B (16384)  -> total 212992
// ---------------------------------------------------------------------------
#define FA_SQ 0
#define FA_SK 65536
#define FA_SV 131072
#define FA_SP 196608
#define FA_SMEM 212992

__global__ void __launch_bounds__(256, 1) attn_fused(
    const uint8_t* __restrict__ q, const uint8_t* __restrict__ k,
    const uint8_t* __restrict__ v, uint8_t* __restrict__ o28, float sc)
{
    extern __shared__ __align__(16) char smem[];
    const uint32_t sb = smem_u32(smem);
    const uint32_t sQ = sb + FA_SQ, sK = sb + FA_SK;
    const uint32_t sV = sb + FA_SV, sP = sb + FA_SP;

    const int tid  = threadIdx.x;
    const int lane = tid & 31;
    const int wid  = tid >> 5;
    const int wm   = wid >> 1;          // 0..3 (i, 32 rows each)
    const int wn   = wid & 1;           // 0..1 (j / c, 64 each)
    const int bm   = blockIdx.x * 128;  // i-tile
    const int bz   = blockIdx.y;        // batch

    const uint8_t* qg = q + (size_t)bz * CHW + (size_t)bm * 512;
    const uint8_t* kg = k + (size_t)bz * CHW;
    const uint8_t* vg = v + (size_t)bz * CHW;

    // ---- prologue: load Q (resident) and k_0 ----
    #pragma unroll
    for (int t = 0; t < 16; t++) {
        const int idx = tid + t * 256;
        const int row = idx >> 5, u = idx & 31;
        cp16(sQ + row * 512 + ((u ^ (row & 7)) << 4), qg + (size_t)row * 512 + u * 16);
    }
    CP_COMMIT();                         // group: Q
    #pragma unroll
    for (int t = 0; t < 16; t++) {
        const int idx = tid + t * 256;
        const int row = idx >> 5, u = idx & 31;
        cp16(sK + row * 512 + ((u ^ (row & 7)) << 4), kg + (size_t)row * 512 + u * 16);
    }
    CP_COMMIT();                         // group: k_0

    uint32_t oacc[4][2][8][2];
    #pragma unroll
    for (int nc = 0; nc < 4; nc++)
        #pragma unroll
        for (int mi = 0; mi < 2; mi++)
            #pragma unroll
            for (int nj = 0; nj < 8; nj++) {
                oacc[nc][mi][nj][0] = 0u; oacc[nc][mi][nj][1] = 0u;
            }
    float lsum[2][2] = {{0.f, 0.f}, {0.f, 0.f}};

    const uint32_t lrow = lane & 15;
    const uint32_t lu   = lane >> 4;     // 16B unit selector
    const int gid = lane >> 2, tig = lane & 3;

    for (int j = 0; j < 32; j++) {
        // issue v_j (V region free: trailing bar of previous iteration)
        #pragma unroll
        for (int t = 0; t < 16; t++) {
            const int idx = tid + t * 256;
            const int row = idx >> 3, u = idx & 7;   // row = c 0..511
            cp16(sV + row * 128 + ((u ^ (row & 7)) << 4),
                 vg + (size_t)row * HW + j * 128 + u * 16);
        }
        CP_COMMIT();
        CP_WAIT1();                      // k_j (and Q) ready; v_j may be pending
        __syncthreads();

        // ---- S phase: s = q . k_j^T, K = 512 (16 kf), no inner barriers ----
        uint32_t sacc[2][8][2];
        #pragma unroll
        for (int mi = 0; mi < 2; mi++)
            #pragma unroll
            for (int nj = 0; nj < 8; nj++) { sacc[mi][nj][0] = 0u; sacc[mi][nj][1] = 0u; }

        #pragma unroll
        for (int kf = 0; kf < 16; kf++) {
            const uint32_t u = kf * 2 + lu;
            uint32_t ar[2][4];
            #pragma unroll
            for (int mi = 0; mi < 2; mi++) {
                const uint32_t row = wm * 32 + mi * 16 + lrow;
                ldsm_x4(ar[mi], sQ + row * 512 + ((u ^ (row & 7)) << 4));
            }
            uint32_t br[4][4];
            #pragma unroll
            for (int nb = 0; nb < 4; nb++) {
                const uint32_t row = wn * 64 + nb * 16 + lrow;
                ldsm_x4(br[nb], sK + row * 512 + ((u ^ (row & 7)) << 4));
            }
            #pragma unroll
            for (int mi = 0; mi < 2; mi++)
                #pragma unroll
                for (int nj = 0; nj < 8; nj++) {
                    const int nb = nj >> 1, od = nj & 1;
                    mma_f8h(sacc[mi][nj], ar[mi], br[nb][od], br[nb][od + 2]);
                }
        }
        __syncthreads();                 // all warps done reading K

        // issue k_{j+1}
        if (j < 31) {
            #pragma unroll
            for (int t = 0; t < 16; t++) {
                const int idx = tid + t * 256;
                const int row = idx >> 5, u = idx & 31;
                cp16(sK + row * 512 + ((u ^ (row & 7)) << 4),
                     kg + (size_t)((j + 1) * 128 + row) * 512 + u * 16);
            }
            CP_COMMIT();
        }

        // ---- P phase: p = exp2(s*sc) -> fp8 smem; accumulate row sums ----
        #pragma unroll
        for (int mi = 0; mi < 2; mi++) {
            #pragma unroll
            for (int r2 = 0; r2 < 2; r2++) {
                const uint32_t m = wm * 32 + mi * 16 + gid + r2 * 8;
                float rs = 0.f;
                #pragma unroll
                for (int nj = 0; nj < 8; nj++) {
                    const uint32_t n = wn * 64 + nj * 8 + tig * 2;
                    const __half2 h = *reinterpret_cast<const __half2*>(&sacc[mi][nj][r2]);
                    const float2 f = __half22float2(h);
                    const float p0 = exp2f(f.x * sc);
                    const float p1 = exp2f(f.y * sc);
                    rs += p0 + p1;
                    sts16(sP + m * 128 + (((n >> 4) ^ (m & 7)) << 4) + (n & 15),
                          f2_to_e4m3x2(p0, p1));
                }
                lsum[mi][r2] += rs;
            }
        }
        __syncthreads();                 // p visible
        if (j < 31) { CP_WAIT1(); } else { CP_WAIT0(); }   // v_j ready
        __syncthreads();

        // ---- O phase: o += p . v_j^T  (K = 128 j-bytes, 4 kf; 4 c-chunks) ----
        uint32_t pf[4][2][4];
        #pragma unroll
        for (int kf = 0; kf < 4; kf++) {
            const uint32_t u = kf * 2 + lu;
            #pragma unroll
            for (int mi = 0; mi < 2; mi++) {
                const uint32_t row = wm * 32 + mi * 16 + lrow;
                ldsm_x4(pf[kf][mi], sP + row * 128 + ((u ^ (row & 7)) << 4));
            }
        }
        #pragma unroll
        for (int nc = 0; nc < 4; nc++) {
            #pragma unroll
            for (int kf = 0; kf < 4; kf++) {
                const uint32_t u = kf * 2 + lu;
                uint32_t br[4][4];
                #pragma unroll
                for (int nb = 0; nb < 4; nb++) {
                    const uint32_t row = nc * 128 + wn * 64 + nb * 16 + lrow;
                    ldsm_x4(br[nb], sV + row * 128 + ((u ^ (row & 7)) << 4));
                }
                #pragma unroll
                for (int mi = 0; mi < 2; mi++)
                    #pragma unroll
                    for (int nj = 0; nj < 8; nj++) {
                        const int nb = nj >> 1, od = nj & 1;
                        mma_f8h(oacc[nc][mi][nj], pf[kf][mi], br[nb][od], br[nb][od + 2]);
                    }
            }
        }
        __syncthreads();                 // V and P free for next iteration
    }

    // ---- epilogue: reduce row sums across tig + wn (via P scratch), write ----
    #pragma unroll
    for (int mi = 0; mi < 2; mi++) {
        #pragma unroll
        for (int r2 = 0; r2 < 2; r2++) {
            float vv = lsum[mi][r2];
            vv += __shfl_xor_sync(0xffffffffu, vv, 1);
            vv += __shfl_xor_sync(0xffffffffu, vv, 2);
            if (tig == 0)
                stsf(sP + (wn * 128 + wm * 32 + mi * 16 + gid + r2 * 8) * 4, vv);
        }
    }
    __syncthreads();

    #pragma unroll
    for (int mi = 0; mi < 2; mi++) {
        #pragma unroll
        for (int r2 = 0; r2 < 2; r2++) {
            const int m = wm * 32 + mi * 16 + gid + r2 * 8;
            const float rsum = ldsf(sP + m * 4) + ldsf(sP + (128 + m) * 4);
            const float scale = __fdividef(256.f, rsum);
            #pragma unroll
            for (int nc = 0; nc < 4; nc++) {
                #pragma unroll
                for (int nj = 0; nj < 8; nj++) {
                    const int c = nc * 128 + wn * 64 + nj * 8 + tig * 2;
                    const __half2 h = *reinterpret_cast<const __half2*>(&oacc[nc][mi][nj][r2]);
                    const float2 f = __half22float2(h);
                    *reinterpret_cast<uint16_t*>(
                        o28 + ((size_t)bz * HW + bm + m) * 512 + c)
                        = f2_to_e4m3x2(f.x * scale, f.y * scale);
                }
            }
        }
    }
}

// ---------------------------------------------------------------------------
// fp8 GEMM for proj, f16 acc: 128x128 tile, 4 warps (2x2 of 64x64), 128 thr,
// 128-fp8 K-chunks, 3 stages, fragment double-buffering.
// fp32 out = acc * sc + bias_m[m] + addc
// ---------------------------------------------------------------------------
__global__ void __launch_bounds__(128, 2) gemm_f8p(
    const uint8_t* __restrict__ A, const uint8_t* __restrict__ B,
    float* __restrict__ C, const float* __restrict__ bias_m,
    int M, int N, int K, float sc, float addc,
    size_t sA, size_t sB, size_t sC)
{
    extern __shared__ __align__(16) char smem[];
    const uint32_t sb = smem_u32(smem);

    const int tid  = threadIdx.x;
    const int lane = tid & 31;
    const int wid  = tid >> 5;
    const int wm   = wid >> 1;
    const int wn   = wid & 1;
    const int bm = blockIdx.y * 128;
    const int bn = blockIdx.x * 128;

    const uint8_t* Ab = A + (size_t)blockIdx.z * sA + (size_t)bm * K;
    const uint8_t* Bb = B + (size_t)blockIdx.z * sB + (size_t)bn * K;

    uint32_t so[8], gAo[8];
    #pragma unroll
    for (int j = 0; j < 8; j++) {
        const int idx = tid + j * 128;
        const int row = idx >> 3, cc = idx & 7;
        so[j]  = (uint32_t)row * PITCH + cc * 16;
        gAo[j] = (uint32_t)row * K + cc * 16;
    }

    const int nk = K >> 7;

    #pragma unroll
    for (int s = 0; s < 2; s++) {
        const uint32_t kb = (uint32_t)s * 128;
        const uint32_t st = sb + s * STG_SZ;
        #pragma unroll
        for (int j = 0; j < 8; j++) {
            cp16(st + so[j],        Ab + gAo[j] + kb);
            cp16(st + OPSZ + so[j], Bb + gAo[j] + kb);
        }
        CP_COMMIT();
    }

    uint32_t acc[4][8][2];
    #pragma unroll
    for (int i = 0; i < 4; i++)
        #pragma unroll
        for (int j = 0; j < 8; j++) { acc[i][j][0] = 0u; acc[i][j][1] = 0u; }

    const uint32_t lrow = lane & 15;
    const uint32_t lsel = (lane >> 4) * 16;
    const uint32_t arow = (wm * 64 + lrow) * PITCH + lsel;
    const uint32_t brow = (wn * 64 + lrow) * PITCH + lsel;

    int buf = 0;
    for (int ck = 0; ck < nk; ck++) {
        CP_WAIT1();
        __syncthreads();

        if (ck + 2 < nk) {
            const uint32_t kb = (uint32_t)(ck + 2) * 128;
            const uint32_t st = sb + ((buf + 2) % 3) * STG_SZ;
            #pragma unroll
            for (int j = 0; j < 8; j++) {
                cp16(st + so[j],        Ab + gAo[j] + kb);
                cp16(st + OPSZ + so[j], Bb + gAo[j] + kb);
            }
        }
        CP_COMMIT();

        const uint32_t sa  = sb + buf * STG_SZ;
        const uint32_t sbm = sa + OPSZ;

        uint32_t ar[2][4][4], br[2][4][4];
        #pragma unroll
        for (int mi = 0; mi < 4; mi++)
            ldsm_x4(ar[0][mi], sa + arow + mi * 16 * PITCH);
        #pragma unroll
        for (int nb = 0; nb < 4; nb++)
            ldsm_x4(br[0][nb], sbm + brow + nb * 16 * PITCH);

        #pragma unroll
        for (int kf = 0; kf < 4; kf++) {
            const int cur = kf & 1, nxt = cur ^ 1;
            if (kf < 3) {
                const uint32_t kofs = (kf + 1) * 32;
                #pragma unroll
                for (int mi = 0; mi < 4; mi++)
                    ldsm_x4(ar[nxt][mi], sa + arow + mi * 16 * PITCH + kofs);
                #pragma unroll
                for (int nb = 0; nb < 4; nb++)
                    ldsm_x4(br[nxt][nb], sbm + brow + nb * 16 * PITCH + kofs);
            }
            #pragma unroll
            for (int mi = 0; mi < 4; mi++)
                #pragma unroll
                for (int nj = 0; nj < 8; nj++) {
                    const int nb = nj >> 1, od = nj & 1;
                    mma_f8h(acc[mi][nj], ar[cur][mi], br[cur][nb][od], br[cur][nb][od + 2]);
                }
        }
        buf = (buf + 1) % 3;
    }

    const int gid = lane >> 2, tig = lane & 3;
    #pragma unroll
    for (int mi = 0; mi < 4; mi++) {
        #pragma unroll
        for (int r2 = 0; r2 < 2; r2++) {
            const int m = bm + wm * 64 + mi * 16 + gid + r2 * 8;
            const float bmv = bias_m[m] + addc;
            #pragma unroll
            for (int nj = 0; nj < 8; nj++) {
                const int n = bn + wn * 64 + nj * 8 + tig * 2;
                const __half2 h = *reinterpret_cast<const __half2*>(&acc[mi][nj][r2]);
                const float2 f = __half22float2(h);
                *reinterpret_cast<float2*>(
                    C + (size_t)blockIdx.z * sC + (size_t)m * N + n)
                    = make_float2(f.x * sc + bmv, f.y * sc + bmv);
            }
        }
    }
}

// ---------------------------------------------------------------------------
// Launch
// ---------------------------------------------------------------------------
extern "C" void kernel_launch(void* const* d_in, const int* in_sizes, int n_in,
                              void* d_out, int out_size)
{
    const float* x  = (const float*)d_in[0];
    const float* gs = (const float*)d_in[1];
    const float* gb = (const float*)d_in[2];
    const float* wq = (const float*)d_in[3];
    const float* bq = (const float*)d_in[4];
    const float* wk = (const float*)d_in[5];
    const float* bk = (const float*)d_in[6];
    const float* wv = (const float*)d_in[7];
    const float* bv = (const float*)d_in[8];
    const float* wp = (const float*)d_in[9];
    const float* bp = (const float*)d_in[10];
    float* out = (float*)d_out;

    __nv_bfloat16 *xnT, *w;
    uint8_t *q, *k, *v, *o28, *w8;
    float *bqk;
    cudaGetSymbolAddress((void**)&xnT, g_xnT);
    cudaGetSymbolAddress((void**)&q,   g_q);
    cudaGetSymbolAddress((void**)&k,   g_k);
    cudaGetSymbolAddress((void**)&v,   g_v);
    cudaGetSymbolAddress((void**)&o28, g_o28);
    cudaGetSymbolAddress((void**)&w,   g_w);
    cudaGetSymbolAddress((void**)&w8,  g_w8);
    cudaGetSymbolAddress((void**)&bqk, g_bqk);

    cudaFuncSetAttribute(gemm_tc<2>, cudaFuncAttributeMaxDynamicSharedMemorySize, SMEM_TC);
    cudaFuncSetAttribute(gemm_tc<3>, cudaFuncAttributeMaxDynamicSharedMemorySize, SMEM_TC);
    cudaFuncSetAttribute(attn_fused, cudaFuncAttributeMaxDynamicSharedMemorySize, FA_SMEM);
    cudaFuncSetAttribute(gemm_f8p,   cudaFuncAttributeMaxDynamicSharedMemorySize, SMEM_TC);

    // 0) weights -> bf16 (+ wp fp8 x64, concat bias)
    cvt_w_kernel<<<dim3(CC / 256, 4), 256>>>(wq, wk, wv, wp, bq, bk, w, w8, bqk);

    // 1) GroupNorm + transpose fused -> xnT [hw, c] bf16
    groupnorm_t_kernel<<<BATCH * NGRP, 256>>>(x, gs, gb, xnT);

    // 2) merged QK (N=1024), split fp8 outputs q[hw,512], k[hw,512]
    dim3 gQK(1024 / 128, HW / 128, BATCH);
    gemm_tc<3><<<gQK, 256, SMEM_TC>>>(xnT, w, q, k, nullptr, bqk,
                                      HW, 1024, CH, 1.f, CHW, 0, CHW);

    // 3) V -> fp8 [c, hw]
    dim3 gV(HW / 128, CH / 128, BATCH);
    gemm_tc<2><<<gV, 256, SMEM_TC>>>(w + 2 * CC, xnT, v, nullptr, bv, nullptr,
                                     CH, HW, CH, 1.f, 0, CHW, CHW);

    // 4) fused attention: scores + exp + row-sum + attnV + normalize -> o28
    const float sc = 1.4426950408f / sqrtf((float)CH);
    attn_fused<<<dim3(HW / 128, BATCH), 256, FA_SMEM>>>(q, k, v, o28, sc);

    // 5) proj fp8: out = (wp8 @ o28^T)/16384 + bp + 64
    dim3 gP(HW / 128, CH / 128, BATCH);
    gemm_f8p<<<gP, 128, SMEM_TC>>>(w8, o28, out, bp,
                                   CH, HW, CH, 1.f / 16384.f, 64.f, 0, CHW, CHW);
}

// round 16
// speedup vs baseline: 1.0278x; 1.0278x over previous
#include <cuda_runtime.h>
#include <cuda_bf16.h>
#include <cuda_fp16.h>
#include <cuda_fp8.h>
#include <cstdint>
#include <math.h>

#define BATCH 4
#define CH    512
#define HW    4096
#define NGRP  32
#define CPG   16
#define NJT   (HW / 128)

static const size_t CHW = (size_t)CH * HW;
static const size_t SHW = (size_t)HW * HW;
#define CC (CH * CH)

// ---------------- scratch ----------------
__device__ __nv_bfloat16 g_xnT [BATCH * CH * HW];   // [hw, c] bf16
__device__ uint8_t       g_q   [BATCH * CH * HW];   // [hw, c] fp8
__device__ uint8_t       g_k   [BATCH * CH * HW];   // [hw, c] fp8
__device__ uint8_t       g_v   [BATCH * CH * HW];   // [c, hw] fp8
__device__ uint8_t       g_at  [BATCH * HW * HW];   // fp8 p = exp(alpha*s)
__device__ uint8_t       g_o28 [BATCH * CH * HW];   // [hw, c] fp8, x256
__device__ __nv_bfloat16 g_w   [4 * CH * CH];       // wq, wk, wv, wp bf16
__device__ uint8_t       g_w8  [CH * CH];           // wp fp8, x64
__device__ float         g_bqk [1024];              // concat(bq, bk)
__device__ float         g_ps  [BATCH * NJT * HW];  // partial row sums
__device__ float         g_rsum[BATCH * HW];        // softmax denominators

// ---------------- PTX helpers (family-portable) ----------------
__device__ __forceinline__ uint32_t smem_u32(const void* p) {
    uint32_t a;
    asm("{ .reg .u64 t; cvta.to.shared.u64 t, %1; cvt.u32.u64 %0, t; }"
        : "=r"(a) : "l"(p));
    return a;
}
__device__ __forceinline__ void cp16(uint32_t s, const void* g) {
    asm volatile("cp.async.cg.shared.global [%0], [%1], 16;"
                 :: "r"(s), "l"(__cvta_generic_to_global(g)) : "memory");
}
#define CP_COMMIT() asm volatile("cp.async.commit_group;" ::: "memory")
#define CP_WAIT1()  asm volatile("cp.async.wait_group 1;"  ::: "memory")

__device__ __forceinline__ void ldsm_x4(uint32_t* r, uint32_t addr) {
    asm volatile("ldmatrix.sync.aligned.m8n8.x4.shared.b16 {%0,%1,%2,%3}, [%4];"
        : "=r"(r[0]), "=r"(r[1]), "=r"(r[2]), "=r"(r[3]) : "r"(addr));
}
__device__ __forceinline__ void mma16816(float* c, const uint32_t* a,
                                         uint32_t b0, uint32_t b1) {
    asm volatile(
        "mma.sync.aligned.m16n8k16.row.col.f32.bf16.bf16.f32 "
        "{%0,%1,%2,%3}, {%4,%5,%6,%7}, {%8,%9}, {%0,%1,%2,%3};"
        : "+f"(c[0]), "+f"(c[1]), "+f"(c[2]), "+f"(c[3])
        : "r"(a[0]), "r"(a[1]), "r"(a[2]), "r"(a[3]), "r"(b0), "r"(b1));
}
__device__ __forceinline__ void mma_f8h(uint32_t* c, const uint32_t* a,
                                        uint32_t b0, uint32_t b1) {
    asm volatile(
        "mma.sync.aligned.m16n8k32.row.col.f16.e4m3.e4m3.f16 "
        "{%0,%1}, {%2,%3,%4,%5}, {%6,%7}, {%0,%1};"
        : "+r"(c[0]), "+r"(c[1])
        : "r"(a[0]), "r"(a[1]), "r"(a[2]), "r"(a[3]), "r"(b0), "r"(b1));
}
__device__ __forceinline__ uint16_t f2_to_e4m3x2(float x0, float x1) {
    return (uint16_t)__nv_cvt_float2_to_fp8x2(make_float2(x0, x1),
                                              __NV_SATFINITE, __NV_E4M3);
}

// ---------------------------------------------------------------------------
// GroupNorm fused with transpose: x [c, hw] fp32 -> xnT [hw, c] bf16
// ---------------------------------------------------------------------------
__global__ __launch_bounds__(256) void groupnorm_t_kernel(
    const float* __restrict__ x, const float* __restrict__ scale,
    const float* __restrict__ bias, __nv_bfloat16* __restrict__ xnT)
{
    const int b = blockIdx.x / NGRP, g = blockIdx.x % NGRP;
    const size_t base = ((size_t)b * CH + (size_t)g * CPG) * HW;
    const int n4 = CPG * HW / 4;

    const float4* xin = reinterpret_cast<const float4*>(x + base);
    float s = 0.f, ss = 0.f;
    for (int i = threadIdx.x; i < n4; i += 256) {
        float4 t = xin[i];
        s  += t.x + t.y + t.z + t.w;
        ss += t.x * t.x + t.y * t.y + t.z * t.z + t.w * t.w;
    }
    __shared__ float r1[256], r2[256];
    r1[threadIdx.x] = s; r2[threadIdx.x] = ss;
    __syncthreads();
    for (int off = 128; off > 0; off >>= 1) {
        if (threadIdx.x < off) {
            r1[threadIdx.x] += r1[threadIdx.x + off];
            r2[threadIdx.x] += r2[threadIdx.x + off];
        }
        __syncthreads();
    }
    const float inv_n = 1.f / (float)(CPG * HW);
    const float mean = r1[0] * inv_n;
    const float var  = fmaxf(r2[0] * inv_n - mean * mean, 0.f);
    const float rstd = rsqrtf(var + 1e-6f);

    const int cl  = threadIdx.x >> 4;
    const int seg = threadIdx.x & 15;
    const float a = scale[g * CPG + cl] * rstd;
    const float d = bias[g * CPG + cl] - mean * a;

    __shared__ uint16_t tile[16][272];
    const float* xrow = x + base + (size_t)cl * HW;
    __nv_bfloat16* outb = xnT + ((size_t)b * HW) * CH + g * CPG;

    for (int hw0 = 0; hw0 < HW; hw0 += 256) {
        const float4* src = reinterpret_cast<const float4*>(xrow + hw0 + seg * 16);
        #pragma unroll
        for (int j = 0; j < 4; j++) {
            float4 t = src[j];
            __nv_bfloat162 h0 = __floats2bfloat162_rn(t.x * a + d, t.y * a + d);
            __nv_bfloat162 h1 = __floats2bfloat162_rn(t.z * a + d, t.w * a + d);
            *reinterpret_cast<uint32_t*>(&tile[cl][seg * 16 + j * 4])
                = *reinterpret_cast<uint32_t*>(&h0);
            *reinterpret_cast<uint32_t*>(&tile[cl][seg * 16 + j * 4 + 2])
                = *reinterpret_cast<uint32_t*>(&h1);
        }
        __syncthreads();
        uint16_t rowv[16];
        #pragma unroll
        for (int i = 0; i < 16; i++) rowv[i] = tile[i][threadIdx.x];
        uint4* dst = reinterpret_cast<uint4*>(outb + (size_t)(hw0 + threadIdx.x) * CH);
        dst[0] = *reinterpret_cast<uint4*>(&rowv[0]);
        dst[1] = *reinterpret_cast<uint4*>(&rowv[8]);
        __syncthreads();
    }
}

// ---------------------------------------------------------------------------
// weights: fp32 -> bf16; wp also -> fp8 x64; concat(bq,bk)
// ---------------------------------------------------------------------------
__global__ __launch_bounds__(256) void cvt_w_kernel(
    const float* __restrict__ a, const float* __restrict__ b,
    const float* __restrict__ c, const float* __restrict__ d,
    const float* __restrict__ bq, const float* __restrict__ bk,
    __nv_bfloat16* __restrict__ w, uint8_t* __restrict__ w8,
    float* __restrict__ bqk)
{
    const int i = blockIdx.x * 256 + threadIdx.x;
    const float* s = (blockIdx.y == 0) ? a : (blockIdx.y == 1) ? b : (blockIdx.y == 2) ? c : d;
    const float val = s[i];
    w[(size_t)blockIdx.y * CC + i] = __float2bfloat16(val);
    if (blockIdx.y == 3)
        w8[i] = (uint8_t)__nv_cvt_float_to_fp8(val * 64.f, __NV_SATFINITE, __NV_E4M3);
    if (blockIdx.y == 0 && i < 1024)
        bqk[i] = (i < 512) ? bq[i] : bk[i - 512];
}

// ---------------------------------------------------------------------------
// bf16 GEMM: D = A@B^T + bias_n. OT 2 = fp8 out; OT 3 = dual fp8 out.
// 128x128 tile, 8 warps 4Mx2N, 3 stages.
// ---------------------------------------------------------------------------
#define PITCH  144
#define OPSZ   18432
#define STG_SZ 36864
#define SMEM_TC 110592

template<int OT>
__global__ void __launch_bounds__(256, 2) gemm_tc(
    const void* __restrict__ Ag, const void* __restrict__ Bg,
    void* __restrict__ Cout, void* __restrict__ Cout2,
    const float* __restrict__ bias_m, const float* __restrict__ bias_n,
    int M, int N, int K, float alpha,
    size_t sA, size_t sB, size_t sC)
{
    extern __shared__ __align__(16) char smem[];
    const uint32_t sb = smem_u32(smem);

    const int tid  = threadIdx.x;
    const int lane = tid & 31;
    const int wid  = tid >> 5;
    const int wm   = wid >> 1;
    const int wn   = wid & 1;
    const int bm = blockIdx.y * 128;
    const int bn = blockIdx.x * 128;

    const uint8_t* Ab = (const uint8_t*)Ag + ((size_t)blockIdx.z * sA + (size_t)bm * K) * 2;
    const uint8_t* Bb = (const uint8_t*)Bg + ((size_t)blockIdx.z * sB + (size_t)bn * K) * 2;

    int rr[4];
    uint32_t so[4], go[4];
    #pragma unroll
    for (int j = 0; j < 4; j++) {
        const int idx = tid + j * 256;
        rr[j] = idx >> 3;
        const int cc = idx & 7;
        so[j] = (uint32_t)rr[j] * PITCH + cc * 16;
        go[j] = cc * 16;
    }

    const int nk = K >> 6;

    #pragma unroll
    for (int s = 0; s < 2; s++) {
        const uint32_t kb = (uint32_t)s * 128;
        const uint32_t st = sb + s * STG_SZ;
        #pragma unroll
        for (int j = 0; j < 4; j++) {
            cp16(st + so[j],        Ab + (size_t)rr[j] * K * 2 + kb + go[j]);
            cp16(st + OPSZ + so[j], Bb + (size_t)rr[j] * K * 2 + kb + go[j]);
        }
        CP_COMMIT();
    }

    float acc[2][8][4];
    #pragma unroll
    for (int i = 0; i < 2; i++)
        #pragma unroll
        for (int j = 0; j < 8; j++)
            #pragma unroll
            for (int t = 0; t < 4; t++) acc[i][j][t] = 0.f;

    const uint32_t lrow = lane & 15;
    const uint32_t lsel = (lane >> 4) * 16;

    int buf = 0;
    for (int ck = 0; ck < nk; ck++) {
        CP_WAIT1();
        __syncthreads();

        if (ck + 2 < nk) {
            const uint32_t kb = (uint32_t)(ck + 2) * 128;
            const uint32_t st = sb + ((buf + 2) % 3) * STG_SZ;
            #pragma unroll
            for (int j = 0; j < 4; j++) {
                cp16(st + so[j],        Ab + (size_t)rr[j] * K * 2 + kb + go[j]);
                cp16(st + OPSZ + so[j], Bb + (size_t)rr[j] * K * 2 + kb + go[j]);
            }
        }
        CP_COMMIT();

        const uint32_t sa  = sb + buf * STG_SZ;
        const uint32_t sbm = sa + OPSZ;
        #pragma unroll
        for (int kf = 0; kf < 4; kf++) {
            const uint32_t kofs = kf * 32 + lsel;
            uint32_t ar[2][4];
            #pragma unroll
            for (int mi = 0; mi < 2; mi++)
                ldsm_x4(ar[mi], sa + (wm * 32 + mi * 16 + lrow) * PITCH + kofs);
            uint32_t br[4][4];
            #pragma unroll
            for (int nb = 0; nb < 4; nb++)
                ldsm_x4(br[nb], sbm + (wn * 64 + nb * 16 + lrow) * PITCH + kofs);
            #pragma unroll
            for (int mi = 0; mi < 2; mi++)
                #pragma unroll
                for (int nj = 0; nj < 8; nj++) {
                    const int nb = nj >> 1, od = nj & 1;
                    mma16816(acc[mi][nj], ar[mi], br[nb][od], br[nb][od + 2]);
                }
        }
        buf = (buf + 1) % 3;
    }

    const int gid = lane >> 2, tig = lane & 3;
    #pragma unroll
    for (int mi = 0; mi < 2; mi++) {
        #pragma unroll
        for (int r2 = 0; r2 < 2; r2++) {
            const int m = bm + wm * 32 + mi * 16 + gid + r2 * 8;
            const float bmv = bias_m ? bias_m[m] : 0.f;
            #pragma unroll
            for (int nj = 0; nj < 8; nj++) {
                const int n = bn + wn * 64 + nj * 8 + tig * 2;
                float x0 = acc[mi][nj][r2 * 2]     * alpha + bmv;
                float x1 = acc[mi][nj][r2 * 2 + 1] * alpha + bmv;
                if (bias_n) { x0 += bias_n[n]; x1 += bias_n[n + 1]; }
                if (OT == 2) {
                    *reinterpret_cast<uint16_t*>(
                        (uint8_t*)Cout + (size_t)blockIdx.z * sC + (size_t)m * N + n)
                        = f2_to_e4m3x2(x0, x1);
                } else {
                    uint8_t* dst = (n < 512) ? (uint8_t*)Cout : (uint8_t*)Cout2;
                    *reinterpret_cast<uint16_t*>(
                        dst + (size_t)blockIdx.z * sC + (size_t)m * 512 + (n & 511))
                        = f2_to_e4m3x2(x0, x1);
                }
            }
        }
    }
}

// ---------------------------------------------------------------------------
// fp8 GEMM, f16 acc: 128x128 tile, 4 warps (2x2 of 64x64), 128 threads,
// 128-fp8 K-chunks, 3-stage cp.async, fragment double-buffering.
// MODE 0 (scores): p = exp2(s*sc) -> fp8, + partial row sums ps.
// MODE 1 (attnV):  fp8 out = acc * 256/rsum[m]
// MODE 2 (proj):   fp32 out = acc * sc + bias_m[m] + addc
// ---------------------------------------------------------------------------
template<int MODE>
__global__ void __launch_bounds__(128, 2) gemm_f8h(
    const uint8_t* __restrict__ A, const uint8_t* __restrict__ B,
    void* __restrict__ C,
    float* __restrict__ ps, const float* __restrict__ rsum,
    const float* __restrict__ bias_m,
    int M, int N, int K, float sc, float addc,
    size_t sA, size_t sB, size_t sC)
{
    extern __shared__ __align__(16) char smem[];
    const uint32_t sb = smem_u32(smem);

    const int tid  = threadIdx.x;
    const int lane = tid & 31;
    const int wid  = tid >> 5;
    const int wm   = wid >> 1;
    const int wn   = wid & 1;
    const int bm = blockIdx.y * 128;
    const int bn = blockIdx.x * 128;

    const uint8_t* Ab = A + (size_t)blockIdx.z * sA + (size_t)bm * K;
    const uint8_t* Bb = B + (size_t)blockIdx.z * sB + (size_t)bn * K;

    uint32_t so[8], gAo[8];
    #pragma unroll
    for (int j = 0; j < 8; j++) {
        const int idx = tid + j * 128;
        const int row = idx >> 3, cc = idx & 7;
        so[j]  = (uint32_t)row * PITCH + cc * 16;
        gAo[j] = (uint32_t)row * K + cc * 16;
    }

    const int nk = K >> 7;

    #pragma unroll
    for (int s = 0; s < 2; s++) {
        const uint32_t kb = (uint32_t)s * 128;
        const uint32_t st = sb + s * STG_SZ;
        #pragma unroll
        for (int j = 0; j < 8; j++) {
            cp16(st + so[j],        Ab + gAo[j] + kb);
            cp16(st + OPSZ + so[j], Bb + gAo[j] + kb);
        }
        CP_COMMIT();
    }

    uint32_t acc[4][8][2];
    #pragma unroll
    for (int i = 0; i < 4; i++)
        #pragma unroll
        for (int j = 0; j < 8; j++) { acc[i][j][0] = 0u; acc[i][j][1] = 0u; }

    const uint32_t lrow = lane & 15;
    const uint32_t lsel = (lane >> 4) * 16;
    const uint32_t arow = (wm * 64 + lrow) * PITCH + lsel;
    const uint32_t brow = (wn * 64 + lrow) * PITCH + lsel;

    int buf = 0;
    for (int ck = 0; ck < nk; ck++) {
        CP_WAIT1();
        __syncthreads();

        if (ck + 2 < nk) {
            const uint32_t kb = (uint32_t)(ck + 2) * 128;
            const uint32_t st = sb + ((buf + 2) % 3) * STG_SZ;
            #pragma unroll
            for (int j = 0; j < 8; j++) {
                cp16(st + so[j],        Ab + gAo[j] + kb);
                cp16(st + OPSZ + so[j], Bb + gAo[j] + kb);
            }
        }
        CP_COMMIT();

        const uint32_t sa  = sb + buf * STG_SZ;
        const uint32_t sbm = sa + OPSZ;

        uint32_t ar[2][4][4], br[2][4][4];
        #pragma unroll
        for (int mi = 0; mi < 4; mi++)
            ldsm_x4(ar[0][mi], sa + arow + mi * 16 * PITCH);
        #pragma unroll
        for (int nb = 0; nb < 4; nb++)
            ldsm_x4(br[0][nb], sbm + brow + nb * 16 * PITCH);

        #pragma unroll
        for (int kf = 0; kf < 4; kf++) {
            const int cur = kf & 1, nxt = cur ^ 1;
            if (kf < 3) {
                const uint32_t kofs = (kf + 1) * 32;
                #pragma unroll
                for (int mi = 0; mi < 4; mi++)
                    ldsm_x4(ar[nxt][mi], sa + arow + mi * 16 * PITCH + kofs);
                #pragma unroll
                for (int nb = 0; nb < 4; nb++)
                    ldsm_x4(br[nxt][nb], sbm + brow + nb * 16 * PITCH + kofs);
            }
            #pragma unroll
            for (int mi = 0; mi < 4; mi++)
                #pragma unroll
                for (int nj = 0; nj < 8; nj++) {
                    const int nb = nj >> 1, od = nj & 1;
                    mma_f8h(acc[mi][nj], ar[cur][mi], br[cur][nb][od], br[cur][nb][od + 2]);
                }
        }
        buf = (buf + 1) % 3;
    }

    const int gid = lane >> 2, tig = lane & 3;

    if (MODE == 0) {
        float lsum[4][2];
        #pragma unroll
        for (int mi = 0; mi < 4; mi++) { lsum[mi][0] = 0.f; lsum[mi][1] = 0.f; }

        #pragma unroll
        for (int mi = 0; mi < 4; mi++) {
            #pragma unroll
            for (int r2 = 0; r2 < 2; r2++) {
                const int m = bm + wm * 64 + mi * 16 + gid + r2 * 8;
                #pragma unroll
                for (int nj = 0; nj < 8; nj++) {
                    const int n = bn + wn * 64 + nj * 8 + tig * 2;
                    const __half2 h = *reinterpret_cast<const __half2*>(&acc[mi][nj][r2]);
                    const float2 f = __half22float2(h);
                    const float p0 = exp2f(f.x * sc);
                    const float p1 = exp2f(f.y * sc);
                    lsum[mi][r2] += p0 + p1;
                    *reinterpret_cast<uint16_t*>(
                        (uint8_t*)C + (size_t)blockIdx.z * sC + (size_t)m * N + n)
                        = f2_to_e4m3x2(p0, p1);
                }
            }
        }
        float* pss = reinterpret_cast<float*>(smem);
        __syncthreads();
        #pragma unroll
        for (int mi = 0; mi < 4; mi++) {
            #pragma unroll
            for (int r2 = 0; r2 < 2; r2++) {
                float v = lsum[mi][r2];
                v += __shfl_xor_sync(0xffffffffu, v, 1);
                v += __shfl_xor_sync(0xffffffffu, v, 2);
                if (tig == 0)
                    pss[wn * 128 + wm * 64 + mi * 16 + gid + r2 * 8] = v;
            }
        }
        __syncthreads();
        ps[((size_t)blockIdx.z * gridDim.x + blockIdx.x) * (size_t)M + bm + tid]
            = pss[tid] + pss[128 + tid];
    } else if (MODE == 1) {
        #pragma unroll
        for (int mi = 0; mi < 4; mi++) {
            #pragma unroll
            for (int r2 = 0; r2 < 2; r2++) {
                const int m = bm + wm * 64 + mi * 16 + gid + r2 * 8;
                const float scale = __fdividef(256.f, rsum[(size_t)blockIdx.z * M + m]);
                #pragma unroll
                for (int nj = 0; nj < 8; nj++) {
                    const int n = bn + wn * 64 + nj * 8 + tig * 2;
                    const __half2 h = *reinterpret_cast<const __half2*>(&acc[mi][nj][r2]);
                    const float2 f = __half22float2(h);
                    *reinterpret_cast<uint16_t*>(
                        (uint8_t*)C + (size_t)blockIdx.z * sC + (size_t)m * N + n)
                        = f2_to_e4m3x2(f.x * scale, f.y * scale);
                }
            }
        }
    } else {
        #pragma unroll
        for (int mi = 0; mi < 4; mi++) {
            #pragma unroll
            for (int r2 = 0; r2 < 2; r2++) {
                const int m = bm + wm * 64 + mi * 16 + gid + r2 * 8;
                const float bmv = bias_m[m] + addc;
                #pragma unroll
                for (int nj = 0; nj < 8; nj++) {
                    const int n = bn + wn * 64 + nj * 8 + tig * 2;
                    const __half2 h = *reinterpret_cast<const __half2*>(&acc[mi][nj][r2]);
                    const float2 f = __half22float2(h);
                    *reinterpret_cast<float2*>(
                        (float*)C + (size_t)blockIdx.z * sC + (size_t)m * N + n)
                        = make_float2(f.x * sc + bmv, f.y * sc + bmv);
                }
            }
        }
    }
}

// ---------------------------------------------------------------------------
// rsum[b][i] = sum over 32 j-tiles of partial sums
// ---------------------------------------------------------------------------
__global__ __launch_bounds__(256) void rsum_kernel(
    const float* __restrict__ ps, float* __restrict__ rsum)
{
    const int i = blockIdx.x * 256 + threadIdx.x;
    const int b = i >> 12, r = i & (HW - 1);
    float s = 0.f;
    #pragma unroll
    for (int jt = 0; jt < NJT; jt++)
        s += ps[((size_t)b * NJT + jt) * HW + r];
    rsum[i] = s;
}

// ---------------------------------------------------------------------------
// Launch: V-projection forked onto a second stream, overlapping QK + scores.
// ---------------------------------------------------------------------------
extern "C" void kernel_launch(void* const* d_in, const int* in_sizes, int n_in,
                              void* d_out, int out_size)
{
    const float* x  = (const float*)d_in[0];
    const float* gs = (const float*)d_in[1];
    const float* gb = (const float*)d_in[2];
    const float* wq = (const float*)d_in[3];
    const float* bq = (const float*)d_in[4];
    const float* wk = (const float*)d_in[5];
    const float* bk = (const float*)d_in[6];
    const float* wv = (const float*)d_in[7];
    const float* bv = (const float*)d_in[8];
    const float* wp = (const float*)d_in[9];
    const float* bp = (const float*)d_in[10];
    float* out = (float*)d_out;

    __nv_bfloat16 *xnT, *w;
    uint8_t *q, *k, *v, *at, *o28, *w8;
    float *bqk, *ps, *rsum;
    cudaGetSymbolAddress((void**)&xnT,  g_xnT);
    cudaGetSymbolAddress((void**)&q,    g_q);
    cudaGetSymbolAddress((void**)&k,    g_k);
    cudaGetSymbolAddress((void**)&v,    g_v);
    cudaGetSymbolAddress((void**)&at,   g_at);
    cudaGetSymbolAddress((void**)&o28,  g_o28);
    cudaGetSymbolAddress((void**)&w,    g_w);
    cudaGetSymbolAddress((void**)&w8,   g_w8);
    cudaGetSymbolAddress((void**)&bqk,  g_bqk);
    cudaGetSymbolAddress((void**)&ps,   g_ps);
    cudaGetSymbolAddress((void**)&rsum, g_rsum);

    cudaFuncSetAttribute(gemm_tc<2>,  cudaFuncAttributeMaxDynamicSharedMemorySize, SMEM_TC);
    cudaFuncSetAttribute(gemm_tc<3>,  cudaFuncAttributeMaxDynamicSharedMemorySize, SMEM_TC);
    cudaFuncSetAttribute(gemm_f8h<0>, cudaFuncAttributeMaxDynamicSharedMemorySize, SMEM_TC);
    cudaFuncSetAttribute(gemm_f8h<1>, cudaFuncAttributeMaxDynamicSharedMemorySize, SMEM_TC);
    cudaFuncSetAttribute(gemm_f8h<2>, cudaFuncAttributeMaxDynamicSharedMemorySize, SMEM_TC);

    // fork/join stream + events (host-side objects; created per call, no
    // device allocations; tiny host-side cost outside the timed graph replay)
    cudaStream_t s1;
    cudaStreamCreateWithFlags(&s1, cudaStreamNonBlocking);
    cudaEvent_t eFork, eV;
    cudaEventCreateWithFlags(&eFork, cudaEventDisableTiming);
    cudaEventCreateWithFlags(&eV,    cudaEventDisableTiming);

    // 0) weights -> bf16 (+ wp fp8 x64, concat bias)    [stream 0]
    cvt_w_kernel<<<dim3(CC / 256, 4), 256>>>(wq, wk, wv, wp, bq, bk, w, w8, bqk);

    // 1) GroupNorm + transpose fused -> xnT              [stream 0]
    groupnorm_t_kernel<<<BATCH * NGRP, 256>>>(x, gs, gb, xnT);

    // fork: s1 depends on (cvt_w, GN)
    cudaEventRecord(eFork, 0);
    cudaStreamWaitEvent(s1, eFork, 0);

    // 2) V -> fp8 [c, hw]                                [stream s1, overlapped]
    dim3 gV(HW / 128, CH / 128, BATCH);
    gemm_tc<2><<<gV, 256, SMEM_TC, s1>>>(w + 2 * CC, xnT, v, nullptr, bv, nullptr,
                                         CH, HW, CH, 1.f, 0, CHW, CHW);
    cudaEventRecord(eV, s1);

    // 3) merged QK (N=1024), split fp8 outputs           [stream 0]
    dim3 gQK(1024 / 128, HW / 128, BATCH);
    gemm_tc<3><<<gQK, 256, SMEM_TC>>>(xnT, w, q, k, nullptr, bqk,
                                      HW, 1024, CH, 1.f, CHW, 0, CHW);

    // 4) scores + exp fused -> fp8 p, partial row sums   [stream 0]
    const float sc = 1.4426950408f / sqrtf((float)CH);
    dim3 gS(HW / 128, HW / 128, BATCH);
    gemm_f8h<0><<<gS, 128, SMEM_TC>>>(q, k, at, ps, nullptr, nullptr,
                                      HW, HW, CH, sc, 0.f, CHW, CHW, SHW);

    // 5) reduce partials -> rsum                         [stream 0]
    rsum_kernel<<<BATCH * HW / 256, 256>>>(ps, rsum);

    // join: attnV needs V
    cudaStreamWaitEvent(0, eV, 0);

    // 6) o28[hw, c] = (p @ v^T) * 256 / rsum             [stream 0]
    dim3 gO(CH / 128, HW / 128, BATCH);
    gemm_f8h<1><<<gO, 128, SMEM_TC>>>(at, v, o28, nullptr, rsum, nullptr,
                                      HW, CH, HW, 0.f, 0.f, SHW, CHW, CHW);

    // 7) proj fp8: out = (wp8 @ o28^T)/16384 + bp + 64   [stream 0]
    dim3 gP(HW / 128, CH / 128, BATCH);
    gemm_f8h<2><<<gP, 128, SMEM_TC>>>(w8, o28, out, nullptr, nullptr, bp,
                                      CH, HW, CH, 1.f / 16384.f, 64.f, 0, CHW, CHW);
}